// round 11
// baseline (speedup 1.0000x reference)
#include <cuda_runtime.h>
#include <cuda_bf16.h>

#define IMG_S   4096
#define N_DOTS  100
#define TW      64
#define TH      32
#define TILES_X (IMG_S / TW)          // 64
#define N_TILES (TILES_X * (IMG_S / TH))  // 8192
#define NTHREADS 256
#define NBLOCKS  888                  // 6 per SM x 148 SMs -> single wave

// Persistent blocks: each block loops over tiles (grid-stride). Per tile,
// thread t: row y = ty0 + (t>>3), x = tx0 + (t&7)*4, quads +0/+32.
__global__ __launch_bounds__(NTHREADS, 6)
void PatchTrainer_dots_kernel(const float* __restrict__ patch,
                              const float* __restrict__ centers,
                              const float* __restrict__ radii,
                              const float* __restrict__ colors,
                              float* __restrict__ out) {
    __shared__ float4   sdot[N_DOTS];   // (xc, yc, r2, idx) descending, truncated
    __shared__ float    scol[N_DOTS * 3];
    __shared__ unsigned s_inter[4];
    __shared__ unsigned s_cont[4];

    const int tid = threadIdx.x;

    // ---- hoisted, tile-invariant: transform dot params + colors (once) ----
    float xc = 0.f, yc = 0.f, r2 = 0.f;
    if (tid < N_DOTS) {
        xc = floorf(__fmul_rn(centers[2 * tid + 0], 4096.0f));
        yc = floorf(__fmul_rn(centers[2 * tid + 1], 4096.0f));
        const float r = floorf(__fmul_rn(radii[tid], 819.2f));
        r2 = __fmul_rn(r, r);
        scol[3 * tid + 0] = colors[3 * tid + 0];
        scol[3 * tid + 1] = colors[3 * tid + 1];
        scol[3 * tid + 2] = colors[3 * tid + 2];
    }
    // (first __syncthreads inside the loop publishes scol before any read)

    for (int tile = blockIdx.x; tile < N_TILES; tile += NBLOCKS) {
        const int tx0 = (tile & (TILES_X - 1)) * TW;
        const int ty0 = (tile >> 6) * TH;

        // ---- per-tile cull (registers only; reference rounding chains) ----
        bool inter = false, cont = false;
        if (tid < N_DOTS) {
            const float fx0 = (float)tx0, fx1 = (float)(tx0 + TW - 1);
            const float fy0 = (float)ty0, fy1 = (float)(ty0 + TH - 1);

            // Intersect: nearest tile pixel (monotone rounding => safe).
            const float nx = fminf(fmaxf(xc, fx0), fx1);
            const float ny = fminf(fmaxf(yc, fy0), fy1);
            const float ndx = __fadd_rn(nx, -xc), ndy = __fadd_rn(ny, -yc);
            inter = __fadd_rn(__fmul_rn(ndx, ndx), __fmul_rn(ndy, ndy)) <= r2;

            // Contains: farthest corner |dx|,|dy|, same chain.
            const float ax = fmaxf(fabsf(__fadd_rn(fx0, -xc)),
                                   fabsf(__fadd_rn(fx1, -xc)));
            const float ay = fmaxf(fabsf(__fadd_rn(fy0, -yc)),
                                   fabsf(__fadd_rn(fy1, -yc)));
            cont = __fadd_rn(__fmul_rn(ax, ax), __fmul_rn(ay, ay)) <= r2;
        }
        const unsigned bi = __ballot_sync(0xffffffffu, inter);
        const unsigned bc = __ballot_sync(0xffffffffu, cont);
        if ((tid & 31) == 0 && tid < 128) {
            s_inter[tid >> 5] = bi;
            s_cont[tid >> 5]  = bc;
        }
        __syncthreads();   // masks published; also orders vs prev tile's sdot reads

        // ---- base + truncated eligible masks ----
        const unsigned cw0 = s_cont[0], cw1 = s_cont[1],
                       cw2 = s_cont[2], cw3 = s_cont[3];
        int base = -1;
        if      (cw3) base = 96 + 31 - __clz(cw3);
        else if (cw2) base = 64 + 31 - __clz(cw2);
        else if (cw1) base = 32 + 31 - __clz(cw1);
        else if (cw0) base =      31 - __clz(cw0);

        unsigned e0 = s_inter[0], e1 = s_inter[1],
                 e2 = s_inter[2], e3 = s_inter[3];
        if (base >= 0) {
            const int bw = base >> 5;
            const unsigned keep = 0xffffffffu << (base & 31);
            if      (bw == 0) { e0 &= keep; }
            else if (bw == 1) { e0 = 0; e1 &= keep; }
            else if (bw == 2) { e0 = 0; e1 = 0; e2 &= keep; }
            else              { e0 = 0; e1 = 0; e2 = 0; e3 &= keep; }
        }
        const int cnt = __popc(e0) + __popc(e1) + __popc(e2) + __popc(e3);

        // ---- parallel compaction into descending list ----
        if (tid < N_DOTS && inter && (base < 0 || tid >= base)) {
            const int w = tid >> 5, b = tid & 31;
            const unsigned own = (w == 0) ? e0 : (w == 1) ? e1 :
                                 (w == 2) ? e2 : e3;
            int rank = __popc(own & (0xFFFFFFFEu << b));
            if (w < 1) rank += __popc(e1);
            if (w < 2) rank += __popc(e2);
            if (w < 3) rank += __popc(e3);
            sdot[rank] = make_float4(xc, yc, r2, __int_as_float(tid));
        }
        __syncthreads();

        const int x = tx0 + ((tid & 7) << 2);
        const int y = ty0 + (tid >> 3);
        const size_t pix   = (size_t)y * IMG_S + (size_t)x;
        const size_t plane = (size_t)IMG_S * IMG_S;

        // ---- fast path: solid tile (cnt/base block-uniform) ----
        if (base >= 0 && cnt == 1) {
            #pragma unroll
            for (int c = 0; c < 3; ++c) {
                const float col = scol[base * 3 + c];
                const float4 o = make_float4(col, col, col, col);
                __stcs(reinterpret_cast<float4*>(out + c * plane + pix),      o);
                __stcs(reinterpret_cast<float4*>(out + c * plane + pix + 32), o);
            }
            continue;
        }

        // ---- fast path: untouched tile (pure copy) ----
        if (cnt == 0) {
            #pragma unroll
            for (int c = 0; c < 3; ++c) {
                float4 a = *reinterpret_cast<const float4*>(patch + c * plane + pix);
                float4 b = *reinterpret_cast<const float4*>(patch + c * plane + pix + 32);
                __stcs(reinterpret_cast<float4*>(out + c * plane + pix),      a);
                __stcs(reinterpret_cast<float4*>(out + c * plane + pix + 32), b);
            }
            continue;
        }

        // ---- per-pixel descending loop over compacted list ----
        const float yf  = (float)y;
        const float x0f = (float)x;

        int b0 = -1, b1 = -1, b2 = -1, b3 = -1,
            b4 = -1, b5 = -1, b6 = -1, b7 = -1;

        for (int k = 0; k < cnt; ++k) {
            const float4 dv = sdot[k];
            const int    d  = __float_as_int(dv.w);

            const float dy  = __fadd_rn(yf, -dv.y);
            const float dy2 = __fmul_rn(dy, dy);
            const float dx0 = __fadd_rn(x0f, -dv.x);
            // exact integer offsets in f32
            const float dx1 = dx0 + 1.0f,  dx2 = dx0 + 2.0f,  dx3 = dx0 + 3.0f;
            const float dx4 = dx0 + 32.0f, dx5 = dx0 + 33.0f,
                        dx6 = dx0 + 34.0f, dx7 = dx0 + 35.0f;

            if (b0 < 0 && __fadd_rn(__fmul_rn(dx0, dx0), dy2) <= dv.z) b0 = d;
            if (b1 < 0 && __fadd_rn(__fmul_rn(dx1, dx1), dy2) <= dv.z) b1 = d;
            if (b2 < 0 && __fadd_rn(__fmul_rn(dx2, dx2), dy2) <= dv.z) b2 = d;
            if (b3 < 0 && __fadd_rn(__fmul_rn(dx3, dx3), dy2) <= dv.z) b3 = d;
            if (b4 < 0 && __fadd_rn(__fmul_rn(dx4, dx4), dy2) <= dv.z) b4 = d;
            if (b5 < 0 && __fadd_rn(__fmul_rn(dx5, dx5), dy2) <= dv.z) b5 = d;
            if (b6 < 0 && __fadd_rn(__fmul_rn(dx6, dx6), dy2) <= dv.z) b6 = d;
            if (b7 < 0 && __fadd_rn(__fmul_rn(dx7, dx7), dy2) <= dv.z) b7 = d;

            const int mn = min(min(min(b0, b1), min(b2, b3)),
                               min(min(b4, b5), min(b6, b7)));
            if (__all_sync(0xffffffffu, mn >= 0)) break;
        }

        // ---- general emit: per-channel scalar color gathers ----
        const bool lo_in = (b0 < 0) | (b1 < 0) | (b2 < 0) | (b3 < 0);
        const bool hi_in = (b4 < 0) | (b5 < 0) | (b6 < 0) | (b7 < 0);

        const int i0 = max(b0, 0) * 3, i1 = max(b1, 0) * 3;
        const int i2 = max(b2, 0) * 3, i3 = max(b3, 0) * 3;
        const int i4 = max(b4, 0) * 3, i5 = max(b5, 0) * 3;
        const int i6 = max(b6, 0) * 3, i7 = max(b7, 0) * 3;

        #pragma unroll
        for (int c = 0; c < 3; ++c) {
            float4 vlo = make_float4(0.f, 0.f, 0.f, 0.f);
            float4 vhi = make_float4(0.f, 0.f, 0.f, 0.f);
            if (lo_in) vlo = *reinterpret_cast<const float4*>(patch + c * plane + pix);
            if (hi_in) vhi = *reinterpret_cast<const float4*>(patch + c * plane + pix + 32);

            float4 o, p;
            o.x = (b0 >= 0) ? scol[i0 + c] : vlo.x;
            o.y = (b1 >= 0) ? scol[i1 + c] : vlo.y;
            o.z = (b2 >= 0) ? scol[i2 + c] : vlo.z;
            o.w = (b3 >= 0) ? scol[i3 + c] : vlo.w;
            p.x = (b4 >= 0) ? scol[i4 + c] : vhi.x;
            p.y = (b5 >= 0) ? scol[i5 + c] : vhi.y;
            p.z = (b6 >= 0) ? scol[i6 + c] : vhi.z;
            p.w = (b7 >= 0) ? scol[i7 + c] : vhi.w;

            __stcs(reinterpret_cast<float4*>(out + c * plane + pix),      o);
            __stcs(reinterpret_cast<float4*>(out + c * plane + pix + 32), p);
        }
    }
}

extern "C" void kernel_launch(void* const* d_in, const int* in_sizes, int n_in,
                              void* d_out, int out_size) {
    const float* adv_patch = (const float*)d_in[0];
    const float* centers   = (const float*)d_in[1];
    const float* radii     = (const float*)d_in[2];
    const float* colors    = (const float*)d_in[3];
    float* out = (float*)d_out;

    PatchTrainer_dots_kernel<<<NBLOCKS, NTHREADS>>>(adv_patch, centers, radii,
                                                    colors, out);
}

// round 12
// speedup vs baseline: 1.1375x; 1.1375x over previous
#include <cuda_runtime.h>
#include <cuda_bf16.h>

#define IMG_S   4096
#define N_DOTS  100
#define TW      64
#define TH      32
#define NTHREADS 256

// Block = 64x32 tile. Thread t: row y = ty0 + (t>>3), x0 = tx0 + (t&7)*4,
// handles two float4 quads at x0 and x0+32 (same row -> shared dy^2).
__global__ __launch_bounds__(NTHREADS, 6)
void PatchTrainer_dots_kernel(const float* __restrict__ patch,
                              const float* __restrict__ centers,
                              const float* __restrict__ radii,
                              const float* __restrict__ colors,
                              float* __restrict__ out) {
    __shared__ float4   sdot[N_DOTS];   // (xc, yc, r2, idx) descending, truncated
    __shared__ float    scol[N_DOTS * 3];
    __shared__ unsigned s_inter[4];
    __shared__ unsigned s_cont[4];

    const int tid = threadIdx.x;
    const int tx0 = blockIdx.x * TW;
    const int ty0 = blockIdx.y * TH;

    // ---- transform + cull: thread d < 100 owns dot d ----
    float xc = 0.f, yc = 0.f, r2 = 0.f;
    bool inter = false, cont = false;
    if (tid < N_DOTS) {
        xc = floorf(__fmul_rn(centers[2 * tid + 0], 4096.0f));
        yc = floorf(__fmul_rn(centers[2 * tid + 1], 4096.0f));
        float r = floorf(__fmul_rn(radii[tid], 819.2f));
        r2 = __fmul_rn(r, r);
        scol[3 * tid + 0] = colors[3 * tid + 0];
        scol[3 * tid + 1] = colors[3 * tid + 1];
        scol[3 * tid + 2] = colors[3 * tid + 2];

        // Intersect: nearest tile pixel, reference rounding chain (monotone
        // rounding => never misses a covered pixel).
        float nx = fminf(fmaxf(xc, (float)tx0), (float)(tx0 + TW - 1));
        float ny = fminf(fmaxf(yc, (float)ty0), (float)(ty0 + TH - 1));
        float ndx = __fadd_rn(nx, -xc), ndy = __fadd_rn(ny, -yc);
        inter = __fadd_rn(__fmul_rn(ndx, ndx), __fmul_rn(ndy, ndy)) <= r2;

        // Contains: farthest corner |dx|,|dy|, same rounding chain.
        float ax = fmaxf(fabsf(__fadd_rn((float)tx0, -xc)),
                         fabsf(__fadd_rn((float)(tx0 + TW - 1), -xc)));
        float ay = fmaxf(fabsf(__fadd_rn((float)ty0, -yc)),
                         fabsf(__fadd_rn((float)(ty0 + TH - 1), -yc)));
        cont = __fadd_rn(__fmul_rn(ax, ax), __fmul_rn(ay, ay)) <= r2;
    }
    unsigned bi = __ballot_sync(0xffffffffu, inter);
    unsigned bc = __ballot_sync(0xffffffffu, cont);
    if ((tid & 31) == 0 && tid < 128) {
        s_inter[tid >> 5] = bi;
        s_cont[tid >> 5]  = bc;
    }
    __syncthreads();

    // ---- base (highest containing dot) + eligible masks, all threads ----
    const unsigned cw0 = s_cont[0], cw1 = s_cont[1], cw2 = s_cont[2], cw3 = s_cont[3];
    int base = -1;
    if      (cw3) base = 96 + 31 - __clz(cw3);
    else if (cw2) base = 64 + 31 - __clz(cw2);
    else if (cw1) base = 32 + 31 - __clz(cw1);
    else if (cw0) base =      31 - __clz(cw0);

    unsigned e0 = s_inter[0], e1 = s_inter[1], e2 = s_inter[2], e3 = s_inter[3];
    if (base >= 0) {
        const int bw = base >> 5;
        const unsigned keep = 0xffffffffu << (base & 31);
        if      (bw == 0) { e0 &= keep; }
        else if (bw == 1) { e0 = 0; e1 &= keep; }
        else if (bw == 2) { e0 = 0; e1 = 0; e2 &= keep; }
        else              { e0 = 0; e1 = 0; e2 = 0; e3 &= keep; }
    }
    const int cnt = __popc(e0) + __popc(e1) + __popc(e2) + __popc(e3);

    // ---- parallel compaction into descending list ----
    if (tid < N_DOTS && inter && (base < 0 || tid >= base)) {
        const int w = tid >> 5, b = tid & 31;
        const unsigned own = (w == 0) ? e0 : (w == 1) ? e1 : (w == 2) ? e2 : e3;
        int rank = __popc(own & (0xFFFFFFFEu << b));
        if (w < 1) rank += __popc(e1);
        if (w < 2) rank += __popc(e2);
        if (w < 3) rank += __popc(e3);
        sdot[rank] = make_float4(xc, yc, r2, __int_as_float(tid));
    }
    __syncthreads();

    const int x = tx0 + ((tid & 7) << 2);
    const int y = ty0 + (tid >> 3);
    const size_t pix   = (size_t)y * IMG_S + (size_t)x;
    const size_t plane = (size_t)IMG_S * IMG_S;

    // ---- fast path: solid tile ----
    if (base >= 0 && cnt == 1) {
        #pragma unroll
        for (int c = 0; c < 3; ++c) {
            const float col = scol[base * 3 + c];
            const float4 o = make_float4(col, col, col, col);
            __stcs(reinterpret_cast<float4*>(out + c * plane + pix),      o);
            __stcs(reinterpret_cast<float4*>(out + c * plane + pix + 32), o);
        }
        return;
    }

    // ---- fast path: untouched tile (pure copy) ----
    if (cnt == 0) {
        #pragma unroll
        for (int c = 0; c < 3; ++c) {
            float4 a = *reinterpret_cast<const float4*>(patch + c * plane + pix);
            float4 b = *reinterpret_cast<const float4*>(patch + c * plane + pix + 32);
            __stcs(reinterpret_cast<float4*>(out + c * plane + pix),      a);
            __stcs(reinterpret_cast<float4*>(out + c * plane + pix + 32), b);
        }
        return;
    }

    // ---- per-pixel descending loop over compacted list ----
    const float yf  = (float)y;
    const float x0f = (float)x;

    int b0 = -1, b1 = -1, b2 = -1, b3 = -1, b4 = -1, b5 = -1, b6 = -1, b7 = -1;

    for (int k = 0; k < cnt; ++k) {
        const float4 dv = sdot[k];
        const int    d  = __float_as_int(dv.w);

        const float dy  = __fadd_rn(yf, -dv.y);
        const float dy2 = __fmul_rn(dy, dy);
        const float dx0 = __fadd_rn(x0f, -dv.x);
        // exact integer offsets in f32
        const float dx1 = dx0 + 1.0f,  dx2 = dx0 + 2.0f,  dx3 = dx0 + 3.0f;
        const float dx4 = dx0 + 32.0f, dx5 = dx0 + 33.0f, dx6 = dx0 + 34.0f, dx7 = dx0 + 35.0f;

        if (b0 < 0 && __fadd_rn(__fmul_rn(dx0, dx0), dy2) <= dv.z) b0 = d;
        if (b1 < 0 && __fadd_rn(__fmul_rn(dx1, dx1), dy2) <= dv.z) b1 = d;
        if (b2 < 0 && __fadd_rn(__fmul_rn(dx2, dx2), dy2) <= dv.z) b2 = d;
        if (b3 < 0 && __fadd_rn(__fmul_rn(dx3, dx3), dy2) <= dv.z) b3 = d;
        if (b4 < 0 && __fadd_rn(__fmul_rn(dx4, dx4), dy2) <= dv.z) b4 = d;
        if (b5 < 0 && __fadd_rn(__fmul_rn(dx5, dx5), dy2) <= dv.z) b5 = d;
        if (b6 < 0 && __fadd_rn(__fmul_rn(dx6, dx6), dy2) <= dv.z) b6 = d;
        if (b7 < 0 && __fadd_rn(__fmul_rn(dx7, dx7), dy2) <= dv.z) b7 = d;

        const int mn = min(min(min(b0, b1), min(b2, b3)),
                           min(min(b4, b5), min(b6, b7)));
        if (__all_sync(0xffffffffu, mn >= 0)) break;
    }

    // ---- emit: per-channel scalar color gathers (short-lived registers) ----
    const bool lo_in = (b0 < 0) | (b1 < 0) | (b2 < 0) | (b3 < 0);
    const bool hi_in = (b4 < 0) | (b5 < 0) | (b6 < 0) | (b7 < 0);

    const int i0 = max(b0, 0) * 3, i1 = max(b1, 0) * 3;
    const int i2 = max(b2, 0) * 3, i3 = max(b3, 0) * 3;
    const int i4 = max(b4, 0) * 3, i5 = max(b5, 0) * 3;
    const int i6 = max(b6, 0) * 3, i7 = max(b7, 0) * 3;

    #pragma unroll
    for (int c = 0; c < 3; ++c) {
        float4 vlo = make_float4(0.f, 0.f, 0.f, 0.f);
        float4 vhi = make_float4(0.f, 0.f, 0.f, 0.f);
        if (lo_in) vlo = *reinterpret_cast<const float4*>(patch + c * plane + pix);
        if (hi_in) vhi = *reinterpret_cast<const float4*>(patch + c * plane + pix + 32);

        float4 o, p;
        o.x = (b0 >= 0) ? scol[i0 + c] : vlo.x;
        o.y = (b1 >= 0) ? scol[i1 + c] : vlo.y;
        o.z = (b2 >= 0) ? scol[i2 + c] : vlo.z;
        o.w = (b3 >= 0) ? scol[i3 + c] : vlo.w;
        p.x = (b4 >= 0) ? scol[i4 + c] : vhi.x;
        p.y = (b5 >= 0) ? scol[i5 + c] : vhi.y;
        p.z = (b6 >= 0) ? scol[i6 + c] : vhi.z;
        p.w = (b7 >= 0) ? scol[i7 + c] : vhi.w;

        __stcs(reinterpret_cast<float4*>(out + c * plane + pix),      o);
        __stcs(reinterpret_cast<float4*>(out + c * plane + pix + 32), p);
    }
}

extern "C" void kernel_launch(void* const* d_in, const int* in_sizes, int n_in,
                              void* d_out, int out_size) {
    const float* adv_patch = (const float*)d_in[0];
    const float* centers   = (const float*)d_in[1];
    const float* radii     = (const float*)d_in[2];
    const float* colors    = (const float*)d_in[3];
    float* out = (float*)d_out;

    dim3 grid(IMG_S / TW, IMG_S / TH);  // 64 x 128 = 8192 blocks
    PatchTrainer_dots_kernel<<<grid, NTHREADS>>>(adv_patch, centers, radii,
                                                 colors, out);
}

// round 13
// speedup vs baseline: 1.1463x; 1.0078x over previous
#include <cuda_runtime.h>
#include <cuda_bf16.h>

#define IMG_S   4096
#define N_DOTS  100
#define TW      64
#define TH      32
#define NTHREADS 256

// Block = 64x32 tile. Thread t: row y = ty0 + (t>>3), x0 = tx0 + (t&7)*4,
// handles two float4 quads at x0 and x0+32 (same row -> shared dy^2).
__global__ __launch_bounds__(NTHREADS, 6)
void PatchTrainer_dots_kernel(const float* __restrict__ patch,
                              const float* __restrict__ centers,
                              const float* __restrict__ radii,
                              const float* __restrict__ colors,
                              float* __restrict__ out) {
    __shared__ float    sxc[N_DOTS];
    __shared__ float    syc[N_DOTS];
    __shared__ float    sr2[N_DOTS];
    __shared__ float4   sdot[N_DOTS];   // (xc, yc, r2, idx) descending, truncated
    __shared__ float    scol[N_DOTS * 3];
    __shared__ unsigned s_inter[4];
    __shared__ unsigned s_cont[4];

    const int tid = threadIdx.x;
    const int tx0 = blockIdx.x * TW;
    const int ty0 = blockIdx.y * TH;

    // ---- transform + cull: thread d < 100 owns dot d ----
    float xc = 0.f, yc = 0.f, r2 = 0.f;
    bool inter = false, cont = false;
    if (tid < N_DOTS) {
        xc = floorf(__fmul_rn(centers[2 * tid + 0], 4096.0f));
        yc = floorf(__fmul_rn(centers[2 * tid + 1], 4096.0f));
        float r = floorf(__fmul_rn(radii[tid], 819.2f));
        r2 = __fmul_rn(r, r);
        scol[3 * tid + 0] = colors[3 * tid + 0];
        scol[3 * tid + 1] = colors[3 * tid + 1];
        scol[3 * tid + 2] = colors[3 * tid + 2];
        sxc[tid] = xc; syc[tid] = yc; sr2[tid] = r2;

        // Intersect: nearest tile pixel, reference rounding chain (monotone
        // rounding => never misses a covered pixel).
        float nx = fminf(fmaxf(xc, (float)tx0), (float)(tx0 + TW - 1));
        float ny = fminf(fmaxf(yc, (float)ty0), (float)(ty0 + TH - 1));
        float ndx = __fadd_rn(nx, -xc), ndy = __fadd_rn(ny, -yc);
        inter = __fadd_rn(__fmul_rn(ndx, ndx), __fmul_rn(ndy, ndy)) <= r2;

        // Contains: farthest corner |dx|,|dy|, same rounding chain.
        float ax = fmaxf(fabsf(__fadd_rn((float)tx0, -xc)),
                         fabsf(__fadd_rn((float)(tx0 + TW - 1), -xc)));
        float ay = fmaxf(fabsf(__fadd_rn((float)ty0, -yc)),
                         fabsf(__fadd_rn((float)(ty0 + TH - 1), -yc)));
        cont = __fadd_rn(__fmul_rn(ax, ax), __fmul_rn(ay, ay)) <= r2;
    }
    unsigned bi = __ballot_sync(0xffffffffu, inter);
    unsigned bc = __ballot_sync(0xffffffffu, cont);
    if ((tid & 31) == 0 && tid < 128) {
        s_inter[tid >> 5] = bi;
        s_cont[tid >> 5]  = bc;
    }
    __syncthreads();

    // ---- base (highest containing dot) + eligible masks, all threads ----
    const unsigned cw0 = s_cont[0], cw1 = s_cont[1], cw2 = s_cont[2], cw3 = s_cont[3];
    int base = -1;
    if      (cw3) base = 96 + 31 - __clz(cw3);
    else if (cw2) base = 64 + 31 - __clz(cw2);
    else if (cw1) base = 32 + 31 - __clz(cw1);
    else if (cw0) base =      31 - __clz(cw0);

    unsigned e0 = s_inter[0], e1 = s_inter[1], e2 = s_inter[2], e3 = s_inter[3];
    if (base >= 0) {
        const int bw = base >> 5;
        const unsigned keep = 0xffffffffu << (base & 31);
        if      (bw == 0) { e0 &= keep; }
        else if (bw == 1) { e0 = 0; e1 &= keep; }
        else if (bw == 2) { e0 = 0; e1 = 0; e2 &= keep; }
        else              { e0 = 0; e1 = 0; e2 = 0; e3 &= keep; }
    }
    const int cnt = __popc(e0) + __popc(e1) + __popc(e2) + __popc(e3);

    // ---- parallel compaction into descending list ----
    if (tid < N_DOTS && inter && (base < 0 || tid >= base)) {
        const int w = tid >> 5, b = tid & 31;
        const unsigned own = (w == 0) ? e0 : (w == 1) ? e1 : (w == 2) ? e2 : e3;
        int rank = __popc(own & (0xFFFFFFFEu << b));
        if (w < 1) rank += __popc(e1);
        if (w < 2) rank += __popc(e2);
        if (w < 3) rank += __popc(e3);
        sdot[rank] = make_float4(xc, yc, r2, __int_as_float(tid));
    }
    __syncthreads();

    const int x = tx0 + ((tid & 7) << 2);
    const int y = ty0 + (tid >> 3);
    const size_t pix   = (size_t)y * IMG_S + (size_t)x;
    const size_t plane = (size_t)IMG_S * IMG_S;

    // ---- fast path: solid tile ----
    if (base >= 0 && cnt == 1) {
        #pragma unroll
        for (int c = 0; c < 3; ++c) {
            const float col = scol[base * 3 + c];
            const float4 o = make_float4(col, col, col, col);
            __stcs(reinterpret_cast<float4*>(out + c * plane + pix),      o);
            __stcs(reinterpret_cast<float4*>(out + c * plane + pix + 32), o);
        }
        return;
    }

    // ---- fast path: untouched tile (pure copy) ----
    if (cnt == 0) {
        #pragma unroll
        for (int c = 0; c < 3; ++c) {
            float4 a = *reinterpret_cast<const float4*>(patch + c * plane + pix);
            float4 b = *reinterpret_cast<const float4*>(patch + c * plane + pix + 32);
            __stcs(reinterpret_cast<float4*>(out + c * plane + pix),      a);
            __stcs(reinterpret_cast<float4*>(out + c * plane + pix + 32), b);
        }
        return;
    }

    // ---- per-pixel descending loop over compacted list ----
    const float yf  = (float)y;
    const float x0f = (float)x;

    int b0 = -1, b1 = -1, b2 = -1, b3 = -1, b4 = -1, b5 = -1, b6 = -1, b7 = -1;

    for (int k = 0; k < cnt; ++k) {
        const float4 dv = sdot[k];
        const int    d  = __float_as_int(dv.w);

        const float dy  = __fadd_rn(yf, -dv.y);
        const float dy2 = __fmul_rn(dy, dy);
        const float dx0 = __fadd_rn(x0f, -dv.x);
        // exact integer offsets in f32
        const float dx1 = dx0 + 1.0f,  dx2 = dx0 + 2.0f,  dx3 = dx0 + 3.0f;
        const float dx4 = dx0 + 32.0f, dx5 = dx0 + 33.0f, dx6 = dx0 + 34.0f, dx7 = dx0 + 35.0f;

        if (b0 < 0 && __fadd_rn(__fmul_rn(dx0, dx0), dy2) <= dv.z) b0 = d;
        if (b1 < 0 && __fadd_rn(__fmul_rn(dx1, dx1), dy2) <= dv.z) b1 = d;
        if (b2 < 0 && __fadd_rn(__fmul_rn(dx2, dx2), dy2) <= dv.z) b2 = d;
        if (b3 < 0 && __fadd_rn(__fmul_rn(dx3, dx3), dy2) <= dv.z) b3 = d;
        if (b4 < 0 && __fadd_rn(__fmul_rn(dx4, dx4), dy2) <= dv.z) b4 = d;
        if (b5 < 0 && __fadd_rn(__fmul_rn(dx5, dx5), dy2) <= dv.z) b5 = d;
        if (b6 < 0 && __fadd_rn(__fmul_rn(dx6, dx6), dy2) <= dv.z) b6 = d;
        if (b7 < 0 && __fadd_rn(__fmul_rn(dx7, dx7), dy2) <= dv.z) b7 = d;

        const int mn = min(min(min(b0, b1), min(b2, b3)),
                           min(min(b4, b5), min(b6, b7)));
        if (__all_sync(0xffffffffu, mn >= 0)) break;
    }

    // ---- emit: per-channel scalar color gathers (short-lived registers) ----
    const bool lo_in = (b0 < 0) | (b1 < 0) | (b2 < 0) | (b3 < 0);
    const bool hi_in = (b4 < 0) | (b5 < 0) | (b6 < 0) | (b7 < 0);

    const int i0 = max(b0, 0) * 3, i1 = max(b1, 0) * 3;
    const int i2 = max(b2, 0) * 3, i3 = max(b3, 0) * 3;
    const int i4 = max(b4, 0) * 3, i5 = max(b5, 0) * 3;
    const int i6 = max(b6, 0) * 3, i7 = max(b7, 0) * 3;

    #pragma unroll
    for (int c = 0; c < 3; ++c) {
        float4 vlo = make_float4(0.f, 0.f, 0.f, 0.f);
        float4 vhi = make_float4(0.f, 0.f, 0.f, 0.f);
        if (lo_in) vlo = *reinterpret_cast<const float4*>(patch + c * plane + pix);
        if (hi_in) vhi = *reinterpret_cast<const float4*>(patch + c * plane + pix + 32);

        float4 o, p;
        o.x = (b0 >= 0) ? scol[i0 + c] : vlo.x;
        o.y = (b1 >= 0) ? scol[i1 + c] : vlo.y;
        o.z = (b2 >= 0) ? scol[i2 + c] : vlo.z;
        o.w = (b3 >= 0) ? scol[i3 + c] : vlo.w;
        p.x = (b4 >= 0) ? scol[i4 + c] : vhi.x;
        p.y = (b5 >= 0) ? scol[i5 + c] : vhi.y;
        p.z = (b6 >= 0) ? scol[i6 + c] : vhi.z;
        p.w = (b7 >= 0) ? scol[i7 + c] : vhi.w;

        __stcs(reinterpret_cast<float4*>(out + c * plane + pix),      o);
        __stcs(reinterpret_cast<float4*>(out + c * plane + pix + 32), p);
    }
}

extern "C" void kernel_launch(void* const* d_in, const int* in_sizes, int n_in,
                              void* d_out, int out_size) {
    const float* adv_patch = (const float*)d_in[0];
    const float* centers   = (const float*)d_in[1];
    const float* radii     = (const float*)d_in[2];
    const float* colors    = (const float*)d_in[3];
    float* out = (float*)d_out;

    dim3 grid(IMG_S / TW, IMG_S / TH);  // 64 x 128 = 8192 blocks
    PatchTrainer_dots_kernel<<<grid, NTHREADS>>>(adv_patch, centers, radii,
                                                 colors, out);
}